// round 14
// baseline (speedup 1.0000x reference)
#include <cuda_runtime.h>
#include <cuda_bf16.h>
#include <cstdint>

#define NB 65536
#define SS 5
#define KK 4
#define DD 12
#define HH 48
#define NCB 16        // batch rows per LSTM CTA
#define TPB_L 192     // 48 d  x  4 q
#define SWS 194       // padded ull-stride per d row (1552 B, != 0 mod 128)

typedef unsigned long long ull;

__device__ float g_xbuf[SS * HH * NB];        // [s][feat][n]
__device__ float g_hst[2][(size_t)HH * NB];   // final hidden per dir, [d][n]

// ---------------- helpers ----------------
__device__ __forceinline__ float sigf(float x) {
    return __fdividef(1.0f, 1.0f + __expf(-x));
}
__device__ __forceinline__ float tanhf_(float x) {
    return 1.0f - __fdividef(2.0f, __expf(2.0f * x) + 1.0f);
}
__device__ __forceinline__ ull pack2(float lo, float hi) {
    ull r; asm("mov.b64 %0, {%1, %2};" : "=l"(r) : "f"(lo), "f"(hi)); return r;
}
__device__ __forceinline__ void unpack2(ull v, float& lo, float& hi) {
    asm("mov.b64 {%0, %1}, %2;" : "=f"(lo), "=f"(hi) : "l"(v));
}
__device__ __forceinline__ float red2(ull v) {
    float lo, hi; unpack2(v, lo, hi); return lo + hi;
}
__device__ __forceinline__ void fma2(ull& acc, ull a, ull b) {
    asm("fma.rn.f32x2 %0, %1, %2, %0;" : "+l"(acc) : "l"(a), "l"(b));
}

// n (0..15) -> ull position within a 16-ull act row (conflict-free halves)
__device__ __forceinline__ int act_pos16(int n) {
    int q = n >> 2, u = n & 3;
    return (u < 2) ? (q * 2 + u) : (8 + q * 2 + u - 2);
}

// ===========================================================================
// Kernel A: GNN — 4 threads per (n,s) pair, each thread handles TWO pairs
// (ns and ns+32). Weight LDS shared across both items.
// ===========================================================================
#define GTPB 128
#define NSB  64   // (n,s) pairs per block

__global__ __launch_bounds__(GTPB) void gnn_kernel(
    const float* __restrict__ nf, const float* __restrict__ pos,
    const float* __restrict__ att,
    const float* __restrict__ msgw, const float* __restrict__ msgb,
    const float* __restrict__ gwi, const float* __restrict__ gwh,
    const float* __restrict__ gbi, const float* __restrict__ gbh)
{
    __shared__ float      s_mw[144];
    __shared__ float      s_mb[12];
    __shared__ ulonglong2 sRZ[144];
    __shared__ ull        sN [144];
    __shared__ ull        sBR[12], sBZ[12], sBN[12];
    __shared__ float      sMA[NSB * 52];
    __shared__ float      sTR[48 * 72];

    int tid = threadIdx.x;
    int ns  = tid >> 2;      // 0..31
    int k   = tid & 3;
    int s   = blockIdx.y;
    int n0  = blockIdx.x * NSB + ns;
    int n1  = n0 + 32;

    for (int i = tid; i < 144; i += GTPB) {
        s_mw[i] = msgw[i];
        int d = i / 12, e = i - d * 12;
        ulonglong2 t;
        t.x = pack2(gwi[d * 12 + e],        gwh[d * 12 + e]);
        t.y = pack2(gwi[(12 + d) * 12 + e], gwh[(12 + d) * 12 + e]);
        sRZ[i] = t;
        sN[i]  = pack2(gwi[(24 + d) * 12 + e], gwh[(24 + d) * 12 + e]);
    }
    if (tid < 12) {
        s_mb[tid] = msgb[tid];
        sBR[tid] = pack2(gbi[tid] + gbh[tid], 0.f);
        sBZ[tid] = pack2(gbi[12 + tid] + gbh[12 + tid], 0.f);
        sBN[tid] = pack2(gbi[24 + tid], gbh[24 + tid]);
    }

    int base0 = n0 * SS + s, base1 = n1 * SS + s;
    float h0[12], h1[12];
    #pragma unroll
    for (int f = 0; f < 6; f++) {
        h0[f]     = nf [base0 * 24 + k * 6 + f];
        h0[6 + f] = pos[base0 * 24 + k * 6 + f];
        h1[f]     = nf [base1 * 24 + k * 6 + f];
        h1[6 + f] = pos[base1 * 24 + k * 6 + f];
    }
    float4 a40 = *reinterpret_cast<const float4*>(att + (size_t)base0 * 16 + k * 4);
    float4 a41 = *reinterpret_cast<const float4*>(att + (size_t)base1 * 16 + k * 4);

    __syncthreads();   // weights staged

    #pragma unroll 1
    for (int pass = 0; pass < 2; pass++) {
        float ma0[12], ma1[12];
        #pragma unroll
        for (int d = 0; d < 12; d++) {
            float acc0 = s_mb[d], acc1 = s_mb[d];
            #pragma unroll
            for (int e = 0; e < 12; e++) {
                float w = s_mw[d * 12 + e];
                acc0 += w * h0[e];
                acc1 += w * h1[e];
            }
            ma0[d] = acc0; ma1[d] = acc1;
        }
        __syncthreads();   // prior sMA reads done
        #pragma unroll
        for (int d = 0; d < 12; d++) {
            sMA[ns * 52 + k * 12 + d] = ma0[d];
            sMA[(ns + 32) * 52 + k * 12 + d] = ma1[d];
        }
        __syncthreads();

        ull gk0[12], gk1[12];
        {
            const float* m0 = sMA + ns * 52;
            const float* m1 = sMA + (ns + 32) * 52;
            #pragma unroll
            for (int e = 0; e < 12; e++) {
                float mv0 = a40.x * m0[e] + a40.y * m0[12 + e] +
                            a40.z * m0[24 + e] + a40.w * m0[36 + e];
                float mv1 = a41.x * m1[e] + a41.y * m1[12 + e] +
                            a41.z * m1[24 + e] + a41.w * m1[36 + e];
                gk0[e] = pack2(mv0, h0[e]);
                gk1[e] = pack2(mv1, h1[e]);
            }
        }

        float t0[12], t1[12];
        #pragma unroll 1
        for (int d = 0; d < 12; d++) {
            ull aR0 = sBR[d], aZ0 = sBZ[d], aN0 = sBN[d];
            ull aR1 = aR0,   aZ1 = aZ0,   aN1 = aN0;
            const ulonglong2* wrz = sRZ + d * 12;
            const ull*        wn  = sN  + d * 12;
            #pragma unroll
            for (int e = 0; e < 12; e++) {
                ulonglong2 w = wrz[e];
                ull wne = wn[e];
                fma2(aR0, w.x, gk0[e]); fma2(aZ0, w.y, gk0[e]); fma2(aN0, wne, gk0[e]);
                fma2(aR1, w.x, gk1[e]); fma2(aZ1, w.y, gk1[e]); fma2(aN1, wne, gk1[e]);
            }
            {
                float r = sigf(red2(aR0));
                float z = sigf(red2(aZ0));
                float nlo, nhi; unpack2(aN0, nlo, nhi);
                float nn = tanhf_(nlo + r * nhi);
                t0[d] = (1.0f - z) * nn + z * h0[d];
            }
            {
                float r = sigf(red2(aR1));
                float z = sigf(red2(aZ1));
                float nlo, nhi; unpack2(aN1, nlo, nhi);
                float nn = tanhf_(nlo + r * nhi);
                t1[d] = (1.0f - z) * nn + z * h1[d];
            }
        }
        #pragma unroll
        for (int d = 0; d < 12; d++) { h0[d] = t0[d]; h1[d] = t1[d]; }
    }

    // transpose-out: row r = d*4+k (stride 72), cols ns and ns+32
    __syncthreads();
    #pragma unroll
    for (int d = 0; d < 12; d++) {
        sTR[(d * 4 + k) * 72 + ns]      = h0[d];
        sTR[(d * 4 + k) * 72 + ns + 32] = h1[d];
    }
    __syncthreads();
    #pragma unroll
    for (int it = 0; it < 24; it++) {
        int idx = it * GTPB + tid;
        int r = idx >> 6, col = idx & 63;
        g_xbuf[(size_t)(s * HH + r) * NB + blockIdx.x * NSB + col] = sTR[r * 72 + col];
    }
}

// ===========================================================================
// Kernel B: register-tiled bidirectional LSTM; NCB=16, 192 thr, 2 CTAs/SM.
// Mid-step barrier; x staged for st+1 at step top.
// ===========================================================================
#define O_W   0                         /* ull[48*SWS] = 74496 B */
#define O_ACT 74496                     /* ull[96*16]  = 12288 B */
#define O_B   (74496 + 12288)           /* float[192] */
#define SMEM_L (O_B + 768 + 16)

__global__ __launch_bounds__(TPB_L, 2) void lstm_rt_kernel(
    const float* __restrict__ wihF, const float* __restrict__ whhF,
    const float* __restrict__ bihF, const float* __restrict__ bhhF,
    const float* __restrict__ wihB, const float* __restrict__ whhB,
    const float* __restrict__ bihB, const float* __restrict__ bhhB)
{
    extern __shared__ char smc[];
    ull*   sW   = (ull*)(smc + O_W);
    ull*   sAct = (ull*)(smc + O_ACT);   // [row][16] with act_pos16 layout
    float* sB   = (float*)(smc + O_B);

    int tid = threadIdx.x;
    int d = tid >> 2;       // 0..47
    int q = tid & 3;        // 0..3
    int nb = blockIdx.x * NCB;

    #pragma unroll 1
    for (int dir = 0; dir < 2; dir++) {
        const float* wih = dir ? wihB : wihF;
        const float* whh = dir ? whhB : whhF;
        const float* bih = dir ? bihB : bihF;
        const float* bhh = dir ? bhhB : bhhF;

        __syncthreads();   // previous dir fully done
        for (int i = tid; i < 9216; i += TPB_L) {
            int dd = i / 192;
            int r  = i - dd * 192;
            int kp = r >> 2, g = r & 3;
            int k0 = 2 * kp;
            float w0, w1;
            if (k0 < 48) {
                w0 = wih[(g * 48 + dd) * 48 + k0];
                w1 = wih[(g * 48 + dd) * 48 + k0 + 1];
            } else {
                w0 = whh[(g * 48 + dd) * 48 + (k0 - 48)];
                w1 = whh[(g * 48 + dd) * 48 + (k0 - 47)];
            }
            sW[dd * SWS + r] = pack2(w0, w1);
        }
        for (int i = tid; i < 192; i += TPB_L) {
            int dd = i >> 2, g = i & 3;
            sB[i] = bih[g * 48 + dd] + bhh[g * 48 + dd];
        }
        // zero h buf0 (rows 48..71); stage x step0 into x buf0 (rows 0..23)
        {
            int s0 = dir ? (SS - 1) : 0;
            #pragma unroll
            for (int rr = 0; rr < 2; rr++) {
                int i = tid + rr * TPB_L;
                int kp = i >> 4, n = i & 15;
                int p = act_pos16(n);
                sAct[(48 + kp) * 16 + p] = 0ull;
                sAct[kp * 16 + p] =
                    pack2(g_xbuf[(size_t)(s0 * HH + 2 * kp) * NB + nb + n],
                          g_xbuf[(size_t)(s0 * HH + 2 * kp + 1) * NB + nb + n]);
            }
        }
        __syncthreads();

        float b0 = sB[d * 4 + 0], b1 = sB[d * 4 + 1];
        float b2 = sB[d * 4 + 2], b3 = sB[d * 4 + 3];
        float c[4] = {0.f, 0.f, 0.f, 0.f};

        #pragma unroll 1
        for (int st = 0; st < SS; st++) {
            int xbase = (st & 1) * 24;

            // stage x for step st+1 into the opposite buffer (disjoint rows)
            if (st < SS - 1) {
                int nbase = ((st + 1) & 1) * 24;
                int sn = dir ? (SS - 2 - st) : (st + 1);
                #pragma unroll
                for (int rr = 0; rr < 2; rr++) {
                    int i = tid + rr * TPB_L;
                    int kp = i >> 4, n = i & 15;
                    sAct[(nbase + kp) * 16 + act_pos16(n)] =
                        pack2(g_xbuf[(size_t)(sn * HH + 2 * kp) * NB + nb + n],
                              g_xbuf[(size_t)(sn * HH + 2 * kp + 1) * NB + nb + n]);
                }
            }

            ull acc[4][4];
            #pragma unroll
            for (int g = 0; g < 4; g++)
                #pragma unroll
                for (int u = 0; u < 4; u++) acc[g][u] = 0ull;

            const ulonglong2* wrow = (const ulonglong2*)(sW + d * SWS);
            const ull* axr = sAct + xbase * 16;
            const ull* ahr = sAct + (48 + xbase) * 16;

            // x-part
            #pragma unroll
            for (int kp = 0; kp < 24; kp++) {
                ulonglong2 wA = wrow[kp * 2];
                ulonglong2 wB = wrow[kp * 2 + 1];
                ulonglong2 aA = *(const ulonglong2*)(axr + kp * 16 + q * 2);
                ulonglong2 aB = *(const ulonglong2*)(axr + kp * 16 + 8 + q * 2);
                fma2(acc[0][0], wA.x, aA.x); fma2(acc[1][0], wA.y, aA.x);
                fma2(acc[2][0], wB.x, aA.x); fma2(acc[3][0], wB.y, aA.x);
                fma2(acc[0][1], wA.x, aA.y); fma2(acc[1][1], wA.y, aA.y);
                fma2(acc[2][1], wB.x, aA.y); fma2(acc[3][1], wB.y, aA.y);
                fma2(acc[0][2], wA.x, aB.x); fma2(acc[1][2], wA.y, aB.x);
                fma2(acc[2][2], wB.x, aB.x); fma2(acc[3][2], wB.y, aB.x);
                fma2(acc[0][3], wA.x, aB.y); fma2(acc[1][3], wA.y, aB.y);
                fma2(acc[2][3], wB.x, aB.y); fma2(acc[3][3], wB.y, aB.y);
            }

            __syncthreads();   // h_{st} writes (prev tail) + x_{st+1} staging visible

            // h-part
            #pragma unroll
            for (int kp = 0; kp < 24; kp++) {
                ulonglong2 wA = wrow[48 + kp * 2];
                ulonglong2 wB = wrow[48 + kp * 2 + 1];
                ulonglong2 aA = *(const ulonglong2*)(ahr + kp * 16 + q * 2);
                ulonglong2 aB = *(const ulonglong2*)(ahr + kp * 16 + 8 + q * 2);
                fma2(acc[0][0], wA.x, aA.x); fma2(acc[1][0], wA.y, aA.x);
                fma2(acc[2][0], wB.x, aA.x); fma2(acc[3][0], wB.y, aA.x);
                fma2(acc[0][1], wA.x, aA.y); fma2(acc[1][1], wA.y, aA.y);
                fma2(acc[2][1], wB.x, aA.y); fma2(acc[3][1], wB.y, aA.y);
                fma2(acc[0][2], wA.x, aB.x); fma2(acc[1][2], wA.y, aB.x);
                fma2(acc[2][2], wB.x, aB.x); fma2(acc[3][2], wB.y, aB.x);
                fma2(acc[0][3], wA.x, aB.y); fma2(acc[1][3], wA.y, aB.y);
                fma2(acc[2][3], wB.x, aB.y); fma2(acc[3][3], wB.y, aB.y);
            }

            float hv[4];
            #pragma unroll
            for (int u = 0; u < 4; u++) {
                float pI = red2(acc[0][u]) + b0;
                float pF = red2(acc[1][u]) + b1;
                float pG = red2(acc[2][u]) + b2;
                float pO = red2(acc[3][u]) + b3;
                float ig = sigf(pI), fg = sigf(pF);
                float gg = tanhf_(pG), og = sigf(pO);
                float cn = fg * c[u] + ig * gg;
                c[u] = cn;
                hv[u] = og * tanhf_(cn);
            }

            if (st < SS - 1) {
                int nbase = ((st + 1) & 1) * 24;
                float* sAf = (float*)sAct;
                int kp_h = 48 + nbase + (d >> 1), par = d & 1;
                #pragma unroll
                for (int u = 0; u < 4; u++) {
                    int p = act_pos16(q * 4 + u);
                    sAf[(kp_h * 16 + p) * 2 + par] = hv[u];
                }
            } else {
                float4 o4 = make_float4(hv[0], hv[1], hv[2], hv[3]);
                *(float4*)&g_hst[dir][(size_t)d * NB + nb + q * 4] = o4;
            }
            // next step's mid barrier provides the ordering
        } // st
    } // dir
}

// ===========================================================================
// Kernel C: MLP head, one thread per n (f32x2 pairs), smem weights
// ===========================================================================
__global__ __launch_bounds__(256) void mlp_kernel(
    const float* __restrict__ e1w, const float* __restrict__ e1b,
    const float* __restrict__ e2w, const float* __restrict__ e2b,
    const float* __restrict__ e3w, const float* __restrict__ e3b,
    float* __restrict__ out)
{
    __shared__ ull   m1p[2304];
    __shared__ float m1b[48], m2[1728], m2b[36], m3[216], m3b[6];

    int tid = threadIdx.x;
    for (int i = tid; i < 2304; i += 256) {
        int ii = i / 48, j = i - ii * 48;
        m1p[i] = pack2(e1w[ii * 96 + j], e1w[ii * 96 + 48 + j]);
    }
    for (int i = tid; i < 1728; i += 256) m2[i] = e2w[i];
    for (int i = tid; i < 216;  i += 256) m3[i] = e3w[i];
    if (tid < 48) m1b[tid] = e1b[tid];
    if (tid < 36) m2b[tid] = e2b[tid];
    if (tid < 6)  m3b[tid] = e3b[tid];
    __syncthreads();

    int n = blockIdx.x * 256 + tid;

    ull av[48];
    #pragma unroll
    for (int j = 0; j < 48; j++)
        av[j] = pack2(g_hst[0][(size_t)j * NB + n], g_hst[1][(size_t)j * NB + n]);

    float x1l[48];
    #pragma unroll 1
    for (int i = 0; i < 48; i++) {
        ull acc = pack2(m1b[i], 0.f);
        const ull* w = m1p + i * 48;
        #pragma unroll
        for (int j = 0; j < 48; j++) fma2(acc, w[j], av[j]);
        x1l[i] = fmaxf(red2(acc), 0.f);
    }
    #pragma unroll
    for (int j = 0; j < 24; j++) av[j] = pack2(x1l[2*j], x1l[2*j+1]);
    const ull* m2p = (const ull*)m2;
    float x2l[36];
    #pragma unroll 1
    for (int i = 0; i < 36; i++) {
        ull acc = pack2(m2b[i], 0.f);
        const ull* w = m2p + i * 24;
        #pragma unroll
        for (int j = 0; j < 24; j++) fma2(acc, w[j], av[j]);
        x2l[i] = fmaxf(red2(acc), 0.f);
    }
    #pragma unroll
    for (int j = 0; j < 18; j++) av[j] = pack2(x2l[2*j], x2l[2*j+1]);
    const ull* m3p = (const ull*)m3;
    #pragma unroll
    for (int cc = 0; cc < 6; cc++) {
        ull acc = pack2(m3b[cc], 0.f);
        const ull* w = m3p + cc * 18;
        #pragma unroll
        for (int j = 0; j < 18; j++) fma2(acc, w[j], av[j]);
        out[(size_t)n * 6 + cc] = red2(acc);
    }
}

// ===========================================================================
extern "C" void kernel_launch(void* const* d_in, const int* in_sizes, int n_in,
                              void* d_out, int out_size)
{
    const float* nf   = (const float*)d_in[0];
    const float* pos  = (const float*)d_in[1];
    const float* att  = (const float*)d_in[2];
    const float* msgw = (const float*)d_in[3];
    const float* msgb = (const float*)d_in[4];
    const float* gwi  = (const float*)d_in[5];
    const float* gwh  = (const float*)d_in[6];
    const float* gbi  = (const float*)d_in[7];
    const float* gbh  = (const float*)d_in[8];
    const float* wihF = (const float*)d_in[9];
    const float* whhF = (const float*)d_in[10];
    const float* bihF = (const float*)d_in[11];
    const float* bhhF = (const float*)d_in[12];
    const float* wihB = (const float*)d_in[13];
    const float* whhB = (const float*)d_in[14];
    const float* bihB = (const float*)d_in[15];
    const float* bhhB = (const float*)d_in[16];
    const float* e1w  = (const float*)d_in[17];
    const float* e1b  = (const float*)d_in[18];
    const float* e2w  = (const float*)d_in[19];
    const float* e2b  = (const float*)d_in[20];
    const float* e3w  = (const float*)d_in[21];
    const float* e3b  = (const float*)d_in[22];
    float* out = (float*)d_out;

    cudaFuncSetAttribute(lstm_rt_kernel,
                         cudaFuncAttributeMaxDynamicSharedMemorySize, SMEM_L);

    dim3 gA(NB / NSB, SS);
    gnn_kernel<<<gA, GTPB>>>(nf, pos, att, msgw, msgb, gwi, gwh, gbi, gbh);
    lstm_rt_kernel<<<NB / NCB, TPB_L, SMEM_L>>>(
        wihF, whhF, bihF, bhhF, wihB, whhB, bihB, bhhB);
    mlp_kernel<<<NB / 256, 256>>>(e1w, e1b, e2w, e2b, e3w, e3b, out);
}

// round 15
// speedup vs baseline: 1.2684x; 1.2684x over previous
#include <cuda_runtime.h>
#include <cuda_bf16.h>
#include <cstdint>

#define NB 65536
#define SS 5
#define KK 4
#define DD 12
#define HH 48
#define NCB 64        // batch rows per LSTM CTA
#define TPB_L 384     // 48 d  x  8 q (8 n per thread)
#define SWS 194       // padded ull-stride per d row (1552 B, != 0 mod 128)

typedef unsigned long long ull;

__device__ float g_xbuf[SS * HH * NB];        // [s][feat][n]
__device__ float g_hst[2][(size_t)HH * NB];   // final hidden per dir, [d][n]

// ---------------- helpers ----------------
__device__ __forceinline__ float sigf(float x) {
    return __fdividef(1.0f, 1.0f + __expf(-x));
}
__device__ __forceinline__ float tanhf_(float x) {
    return 1.0f - __fdividef(2.0f, __expf(2.0f * x) + 1.0f);
}
__device__ __forceinline__ ull pack2(float lo, float hi) {
    ull r; asm("mov.b64 %0, {%1, %2};" : "=l"(r) : "f"(lo), "f"(hi)); return r;
}
__device__ __forceinline__ void unpack2(ull v, float& lo, float& hi) {
    asm("mov.b64 {%0, %1}, %2;" : "=f"(lo), "=f"(hi) : "l"(v));
}
__device__ __forceinline__ float red2(ull v) {
    float lo, hi; unpack2(v, lo, hi); return lo + hi;
}
__device__ __forceinline__ void fma2(ull& acc, ull a, ull b) {
    asm("fma.rn.f32x2 %0, %1, %2, %0;" : "+l"(acc) : "l"(a), "l"(b));
}

// n (0..63) -> ull position in a 64-ull act row: n = q*8+u,
// p = (u>>1)*16 + q*2 + (u&1)  (4 groups of 128B; each group spans all 8 q)
__device__ __forceinline__ int act_pos64(int n) {
    int q = n >> 3, u = n & 7;
    return ((u >> 1) << 4) + q * 2 + (u & 1);
}

// ===========================================================================
// Kernel A: GNN — 4 threads per (n,s) pair, each thread handles TWO pairs.
// (unchanged from R14: 181us measured)
// ===========================================================================
#define GTPB 128
#define NSB  64

__global__ __launch_bounds__(GTPB) void gnn_kernel(
    const float* __restrict__ nf, const float* __restrict__ pos,
    const float* __restrict__ att,
    const float* __restrict__ msgw, const float* __restrict__ msgb,
    const float* __restrict__ gwi, const float* __restrict__ gwh,
    const float* __restrict__ gbi, const float* __restrict__ gbh)
{
    __shared__ float      s_mw[144];
    __shared__ float      s_mb[12];
    __shared__ ulonglong2 sRZ[144];
    __shared__ ull        sN [144];
    __shared__ ull        sBR[12], sBZ[12], sBN[12];
    __shared__ float      sMA[NSB * 52];
    __shared__ float      sTR[48 * 72];

    int tid = threadIdx.x;
    int ns  = tid >> 2;
    int k   = tid & 3;
    int s   = blockIdx.y;
    int n0  = blockIdx.x * NSB + ns;
    int n1  = n0 + 32;

    for (int i = tid; i < 144; i += GTPB) {
        s_mw[i] = msgw[i];
        int d = i / 12, e = i - d * 12;
        ulonglong2 t;
        t.x = pack2(gwi[d * 12 + e],        gwh[d * 12 + e]);
        t.y = pack2(gwi[(12 + d) * 12 + e], gwh[(12 + d) * 12 + e]);
        sRZ[i] = t;
        sN[i]  = pack2(gwi[(24 + d) * 12 + e], gwh[(24 + d) * 12 + e]);
    }
    if (tid < 12) {
        s_mb[tid] = msgb[tid];
        sBR[tid] = pack2(gbi[tid] + gbh[tid], 0.f);
        sBZ[tid] = pack2(gbi[12 + tid] + gbh[12 + tid], 0.f);
        sBN[tid] = pack2(gbi[24 + tid], gbh[24 + tid]);
    }

    int base0 = n0 * SS + s, base1 = n1 * SS + s;
    float h0[12], h1[12];
    #pragma unroll
    for (int f = 0; f < 6; f++) {
        h0[f]     = nf [base0 * 24 + k * 6 + f];
        h0[6 + f] = pos[base0 * 24 + k * 6 + f];
        h1[f]     = nf [base1 * 24 + k * 6 + f];
        h1[6 + f] = pos[base1 * 24 + k * 6 + f];
    }
    float4 a40 = *reinterpret_cast<const float4*>(att + (size_t)base0 * 16 + k * 4);
    float4 a41 = *reinterpret_cast<const float4*>(att + (size_t)base1 * 16 + k * 4);

    __syncthreads();

    #pragma unroll 1
    for (int pass = 0; pass < 2; pass++) {
        float ma0[12], ma1[12];
        #pragma unroll
        for (int d = 0; d < 12; d++) {
            float acc0 = s_mb[d], acc1 = s_mb[d];
            #pragma unroll
            for (int e = 0; e < 12; e++) {
                float w = s_mw[d * 12 + e];
                acc0 += w * h0[e];
                acc1 += w * h1[e];
            }
            ma0[d] = acc0; ma1[d] = acc1;
        }
        __syncthreads();
        #pragma unroll
        for (int d = 0; d < 12; d++) {
            sMA[ns * 52 + k * 12 + d] = ma0[d];
            sMA[(ns + 32) * 52 + k * 12 + d] = ma1[d];
        }
        __syncthreads();

        ull gk0[12], gk1[12];
        {
            const float* m0 = sMA + ns * 52;
            const float* m1 = sMA + (ns + 32) * 52;
            #pragma unroll
            for (int e = 0; e < 12; e++) {
                float mv0 = a40.x * m0[e] + a40.y * m0[12 + e] +
                            a40.z * m0[24 + e] + a40.w * m0[36 + e];
                float mv1 = a41.x * m1[e] + a41.y * m1[12 + e] +
                            a41.z * m1[24 + e] + a41.w * m1[36 + e];
                gk0[e] = pack2(mv0, h0[e]);
                gk1[e] = pack2(mv1, h1[e]);
            }
        }

        float t0[12], t1[12];
        #pragma unroll 1
        for (int d = 0; d < 12; d++) {
            ull aR0 = sBR[d], aZ0 = sBZ[d], aN0 = sBN[d];
            ull aR1 = aR0,   aZ1 = aZ0,   aN1 = aN0;
            const ulonglong2* wrz = sRZ + d * 12;
            const ull*        wn  = sN  + d * 12;
            #pragma unroll
            for (int e = 0; e < 12; e++) {
                ulonglong2 w = wrz[e];
                ull wne = wn[e];
                fma2(aR0, w.x, gk0[e]); fma2(aZ0, w.y, gk0[e]); fma2(aN0, wne, gk0[e]);
                fma2(aR1, w.x, gk1[e]); fma2(aZ1, w.y, gk1[e]); fma2(aN1, wne, gk1[e]);
            }
            {
                float r = sigf(red2(aR0));
                float z = sigf(red2(aZ0));
                float nlo, nhi; unpack2(aN0, nlo, nhi);
                float nn = tanhf_(nlo + r * nhi);
                t0[d] = (1.0f - z) * nn + z * h0[d];
            }
            {
                float r = sigf(red2(aR1));
                float z = sigf(red2(aZ1));
                float nlo, nhi; unpack2(aN1, nlo, nhi);
                float nn = tanhf_(nlo + r * nhi);
                t1[d] = (1.0f - z) * nn + z * h1[d];
            }
        }
        #pragma unroll
        for (int d = 0; d < 12; d++) { h0[d] = t0[d]; h1[d] = t1[d]; }
    }

    __syncthreads();
    #pragma unroll
    for (int d = 0; d < 12; d++) {
        sTR[(d * 4 + k) * 72 + ns]      = h0[d];
        sTR[(d * 4 + k) * 72 + ns + 32] = h1[d];
    }
    __syncthreads();
    #pragma unroll
    for (int it = 0; it < 24; it++) {
        int idx = it * GTPB + tid;
        int r = idx >> 6, col = idx & 63;
        g_xbuf[(size_t)(s * HH + r) * NB + blockIdx.x * NSB + col] = sTR[r * 72 + col];
    }
}

// ===========================================================================
// Kernel B: register-tiled bidirectional LSTM; NCB=64, 8 n per thread.
// Per kp-iter: 6 LDS feed 32 FFMA2. 1024 CTAs, 1/SM.
// ===========================================================================
#define O_W   0                         /* ull[48*SWS] = 74496 B */
#define O_ACT 74496                     /* ull[96*64]  = 49152 B */
#define O_B   (74496 + 49152)           /* float[192] */
#define SMEM_L (O_B + 768 + 16)

__global__ __launch_bounds__(TPB_L, 1) void lstm_rt_kernel(
    const float* __restrict__ wihF, const float* __restrict__ whhF,
    const float* __restrict__ bihF, const float* __restrict__ bhhF,
    const float* __restrict__ wihB, const float* __restrict__ whhB,
    const float* __restrict__ bihB, const float* __restrict__ bhhB)
{
    extern __shared__ char smc[];
    ull*   sW   = (ull*)(smc + O_W);
    ull*   sAct = (ull*)(smc + O_ACT);   // [row][64] with act_pos64 layout
    float* sB   = (float*)(smc + O_B);

    int tid = threadIdx.x;
    int d = tid >> 3;       // 0..47
    int q = tid & 7;        // 0..7  (n = nb + q*8 + u, u 0..7)
    int nb = blockIdx.x * NCB;

    #pragma unroll 1
    for (int dir = 0; dir < 2; dir++) {
        const float* wih = dir ? wihB : wihF;
        const float* whh = dir ? whhB : whhF;
        const float* bih = dir ? bihB : bihF;
        const float* bhh = dir ? bhhB : bhhF;

        __syncthreads();
        for (int i = tid; i < 9216; i += TPB_L) {
            int dd = i / 192;
            int r  = i - dd * 192;
            int kp = r >> 2, g = r & 3;
            int k0 = 2 * kp;
            float w0, w1;
            if (k0 < 48) {
                w0 = wih[(g * 48 + dd) * 48 + k0];
                w1 = wih[(g * 48 + dd) * 48 + k0 + 1];
            } else {
                w0 = whh[(g * 48 + dd) * 48 + (k0 - 48)];
                w1 = whh[(g * 48 + dd) * 48 + (k0 - 47)];
            }
            sW[dd * SWS + r] = pack2(w0, w1);
        }
        for (int i = tid; i < 192; i += TPB_L) {
            int dd = i >> 2, g = i & 3;
            sB[i] = bih[g * 48 + dd] + bhh[g * 48 + dd];
        }
        // zero h buf0 (rows 48..71); stage x step0 into x buf0 (rows 0..23)
        {
            int s0 = dir ? (SS - 1) : 0;
            #pragma unroll
            for (int rr = 0; rr < 4; rr++) {
                int i = tid + rr * TPB_L;
                int kp = i >> 6, n = i & 63;
                int p = act_pos64(n);
                sAct[(48 + kp) * 64 + p] = 0ull;
                sAct[kp * 64 + p] =
                    pack2(g_xbuf[(size_t)(s0 * HH + 2 * kp) * NB + nb + n],
                          g_xbuf[(size_t)(s0 * HH + 2 * kp + 1) * NB + nb + n]);
            }
        }
        __syncthreads();

        float b0 = sB[d * 4 + 0], b1 = sB[d * 4 + 1];
        float b2 = sB[d * 4 + 2], b3 = sB[d * 4 + 3];
        float c[8];
        #pragma unroll
        for (int u = 0; u < 8; u++) c[u] = 0.f;

        #pragma unroll 1
        for (int st = 0; st < SS; st++) {
            int xbase = (st & 1) * 24;

            // stage x for st+1 into the opposite buffer (x rows; disjoint from
            // straggler h writes of st-1 which touch h rows only)
            if (st < SS - 1) {
                int nbase = ((st + 1) & 1) * 24;
                int sn = dir ? (SS - 2 - st) : (st + 1);
                #pragma unroll
                for (int rr = 0; rr < 4; rr++) {
                    int i = tid + rr * TPB_L;
                    int kp = i >> 6, n = i & 63;
                    sAct[(nbase + kp) * 64 + act_pos64(n)] =
                        pack2(g_xbuf[(size_t)(sn * HH + 2 * kp) * NB + nb + n],
                              g_xbuf[(size_t)(sn * HH + 2 * kp + 1) * NB + nb + n]);
                }
            }

            ull acc[4][8];
            #pragma unroll
            for (int g = 0; g < 4; g++)
                #pragma unroll
                for (int u = 0; u < 8; u++) acc[g][u] = 0ull;

            const ulonglong2* wrow = (const ulonglong2*)(sW + d * SWS);
            const ull* axr = sAct + xbase * 64;
            const ull* ahr = sAct + (48 + xbase) * 64;

            // x-part
            #pragma unroll
            for (int kp = 0; kp < 24; kp++) {
                ulonglong2 wA = wrow[kp * 2];
                ulonglong2 wB = wrow[kp * 2 + 1];
                #pragma unroll
                for (int g4 = 0; g4 < 4; g4++) {
                    ulonglong2 av = *(const ulonglong2*)(axr + kp * 64 + g4 * 16 + q * 2);
                    fma2(acc[0][2*g4],   wA.x, av.x); fma2(acc[1][2*g4],   wA.y, av.x);
                    fma2(acc[2][2*g4],   wB.x, av.x); fma2(acc[3][2*g4],   wB.y, av.x);
                    fma2(acc[0][2*g4+1], wA.x, av.y); fma2(acc[1][2*g4+1], wA.y, av.y);
                    fma2(acc[2][2*g4+1], wB.x, av.y); fma2(acc[3][2*g4+1], wB.y, av.y);
                }
            }

            __syncthreads();   // h_{st} writes (prev tail) + x_{st+1} staging visible

            // h-part
            #pragma unroll
            for (int kp = 0; kp < 24; kp++) {
                ulonglong2 wA = wrow[48 + kp * 2];
                ulonglong2 wB = wrow[48 + kp * 2 + 1];
                #pragma unroll
                for (int g4 = 0; g4 < 4; g4++) {
                    ulonglong2 av = *(const ulonglong2*)(ahr + kp * 64 + g4 * 16 + q * 2);
                    fma2(acc[0][2*g4],   wA.x, av.x); fma2(acc[1][2*g4],   wA.y, av.x);
                    fma2(acc[2][2*g4],   wB.x, av.x); fma2(acc[3][2*g4],   wB.y, av.x);
                    fma2(acc[0][2*g4+1], wA.x, av.y); fma2(acc[1][2*g4+1], wA.y, av.y);
                    fma2(acc[2][2*g4+1], wB.x, av.y); fma2(acc[3][2*g4+1], wB.y, av.y);
                }
            }

            float hv[8];
            #pragma unroll
            for (int u = 0; u < 8; u++) {
                float pI = red2(acc[0][u]) + b0;
                float pF = red2(acc[1][u]) + b1;
                float pG = red2(acc[2][u]) + b2;
                float pO = red2(acc[3][u]) + b3;
                float ig = sigf(pI), fg = sigf(pF);
                float gg = tanhf_(pG), og = sigf(pO);
                float cn = fg * c[u] + ig * gg;
                c[u] = cn;
                hv[u] = og * tanhf_(cn);
            }

            if (st < SS - 1) {
                int nbase = ((st + 1) & 1) * 24;
                float* sAf = (float*)sAct;
                int kp_h = 48 + nbase + (d >> 1), par = d & 1;
                #pragma unroll
                for (int u = 0; u < 8; u++) {
                    int p = ((u >> 1) << 4) + q * 2 + (u & 1);
                    sAf[(kp_h * 64 + p) * 2 + par] = hv[u];
                }
            } else {
                float4 oa = make_float4(hv[0], hv[1], hv[2], hv[3]);
                float4 ob = make_float4(hv[4], hv[5], hv[6], hv[7]);
                *(float4*)&g_hst[dir][(size_t)d * NB + nb + q * 8]     = oa;
                *(float4*)&g_hst[dir][(size_t)d * NB + nb + q * 8 + 4] = ob;
            }
            // next step's mid barrier provides ordering
        } // st
    } // dir
}

// ===========================================================================
// Kernel C: MLP head, one thread per n (f32x2 pairs), smem weights
// ===========================================================================
__global__ __launch_bounds__(256) void mlp_kernel(
    const float* __restrict__ e1w, const float* __restrict__ e1b,
    const float* __restrict__ e2w, const float* __restrict__ e2b,
    const float* __restrict__ e3w, const float* __restrict__ e3b,
    float* __restrict__ out)
{
    __shared__ ull   m1p[2304];
    __shared__ float m1b[48], m2[1728], m2b[36], m3[216], m3b[6];

    int tid = threadIdx.x;
    for (int i = tid; i < 2304; i += 256) {
        int ii = i / 48, j = i - ii * 48;
        m1p[i] = pack2(e1w[ii * 96 + j], e1w[ii * 96 + 48 + j]);
    }
    for (int i = tid; i < 1728; i += 256) m2[i] = e2w[i];
    for (int i = tid; i < 216;  i += 256) m3[i] = e3w[i];
    if (tid < 48) m1b[tid] = e1b[tid];
    if (tid < 36) m2b[tid] = e2b[tid];
    if (tid < 6)  m3b[tid] = e3b[tid];
    __syncthreads();

    int n = blockIdx.x * 256 + tid;

    ull av[48];
    #pragma unroll
    for (int j = 0; j < 48; j++)
        av[j] = pack2(g_hst[0][(size_t)j * NB + n], g_hst[1][(size_t)j * NB + n]);

    float x1l[48];
    #pragma unroll 1
    for (int i = 0; i < 48; i++) {
        ull acc = pack2(m1b[i], 0.f);
        const ull* w = m1p + i * 48;
        #pragma unroll
        for (int j = 0; j < 48; j++) fma2(acc, w[j], av[j]);
        x1l[i] = fmaxf(red2(acc), 0.f);
    }
    #pragma unroll
    for (int j = 0; j < 24; j++) av[j] = pack2(x1l[2*j], x1l[2*j+1]);
    const ull* m2p = (const ull*)m2;
    float x2l[36];
    #pragma unroll 1
    for (int i = 0; i < 36; i++) {
        ull acc = pack2(m2b[i], 0.f);
        const ull* w = m2p + i * 24;
        #pragma unroll
        for (int j = 0; j < 24; j++) fma2(acc, w[j], av[j]);
        x2l[i] = fmaxf(red2(acc), 0.f);
    }
    #pragma unroll
    for (int j = 0; j < 18; j++) av[j] = pack2(x2l[2*j], x2l[2*j+1]);
    const ull* m3p = (const ull*)m3;
    #pragma unroll
    for (int cc = 0; cc < 6; cc++) {
        ull acc = pack2(m3b[cc], 0.f);
        const ull* w = m3p + cc * 18;
        #pragma unroll
        for (int j = 0; j < 18; j++) fma2(acc, w[j], av[j]);
        out[(size_t)n * 6 + cc] = red2(acc);
    }
}

// ===========================================================================
extern "C" void kernel_launch(void* const* d_in, const int* in_sizes, int n_in,
                              void* d_out, int out_size)
{
    const float* nf   = (const float*)d_in[0];
    const float* pos  = (const float*)d_in[1];
    const float* att  = (const float*)d_in[2];
    const float* msgw = (const float*)d_in[3];
    const float* msgb = (const float*)d_in[4];
    const float* gwi  = (const float*)d_in[5];
    const float* gwh  = (const float*)d_in[6];
    const float* gbi  = (const float*)d_in[7];
    const float* gbh  = (const float*)d_in[8];
    const float* wihF = (const float*)d_in[9];
    const float* whhF = (const float*)d_in[10];
    const float* bihF = (const float*)d_in[11];
    const float* bhhF = (const float*)d_in[12];
    const float* wihB = (const float*)d_in[13];
    const float* whhB = (const float*)d_in[14];
    const float* bihB = (const float*)d_in[15];
    const float* bhhB = (const float*)d_in[16];
    const float* e1w  = (const float*)d_in[17];
    const float* e1b  = (const float*)d_in[18];
    const float* e2w  = (const float*)d_in[19];
    const float* e2b  = (const float*)d_in[20];
    const float* e3w  = (const float*)d_in[21];
    const float* e3b  = (const float*)d_in[22];
    float* out = (float*)d_out;

    cudaFuncSetAttribute(lstm_rt_kernel,
                         cudaFuncAttributeMaxDynamicSharedMemorySize, SMEM_L);

    dim3 gA(NB / NSB, SS);
    gnn_kernel<<<gA, GTPB>>>(nf, pos, att, msgw, msgb, gwi, gwh, gbi, gbh);
    lstm_rt_kernel<<<NB / NCB, TPB_L, SMEM_L>>>(
        wihF, whhF, bihF, bhhF, wihB, whhB, bihB, bhhB);
    mlp_kernel<<<NB / 256, 256>>>(e1w, e1b, e2w, e2b, e3w, e3b, out);
}

// round 16
// speedup vs baseline: 1.2786x; 1.0081x over previous
#include <cuda_runtime.h>
#include <cuda_bf16.h>
#include <cstdint>

#define NB 65536
#define SS 5
#define KK 4
#define DD 12
#define HH 48
#define NCB 64        // batch rows per LSTM CTA
#define TPB_L 384     // 48 d  x  8 q (8 n per thread)
#define SWS 194       // padded ull-stride per d row (1552 B, != 0 mod 128)

typedef unsigned long long ull;

__device__ ull   g_xbuf[SS * 24 * NB];        // [s][feat-pair][n] packed pairs
__device__ float g_hst[2][(size_t)HH * NB];   // final hidden per dir, [d][n]

// ---------------- helpers ----------------
__device__ __forceinline__ float sigf(float x) {
    return __fdividef(1.0f, 1.0f + __expf(-x));
}
__device__ __forceinline__ float tanhf_(float x) {
    return 1.0f - __fdividef(2.0f, __expf(2.0f * x) + 1.0f);
}
__device__ __forceinline__ ull pack2(float lo, float hi) {
    ull r; asm("mov.b64 %0, {%1, %2};" : "=l"(r) : "f"(lo), "f"(hi)); return r;
}
__device__ __forceinline__ void unpack2(ull v, float& lo, float& hi) {
    asm("mov.b64 {%0, %1}, %2;" : "=f"(lo), "=f"(hi) : "l"(v));
}
__device__ __forceinline__ float red2(ull v) {
    float lo, hi; unpack2(v, lo, hi); return lo + hi;
}
__device__ __forceinline__ void fma2(ull& acc, ull a, ull b) {
    asm("fma.rn.f32x2 %0, %1, %2, %0;" : "+l"(acc) : "l"(a), "l"(b));
}

// n (0..63) -> ull position in a 64-ull act row
__device__ __forceinline__ int act_pos64(int n) {
    int q = n >> 3, u = n & 7;
    return ((u >> 1) << 4) + q * 2 + (u & 1);
}

// ===========================================================================
// Kernel A: GNN — 4 threads per (n,s) pair, each thread handles TWO pairs.
// Output stored as packed feature-pairs (ull).
// ===========================================================================
#define GTPB 128
#define NSB  64

__global__ __launch_bounds__(GTPB) void gnn_kernel(
    const float* __restrict__ nf, const float* __restrict__ pos,
    const float* __restrict__ att,
    const float* __restrict__ msgw, const float* __restrict__ msgb,
    const float* __restrict__ gwi, const float* __restrict__ gwh,
    const float* __restrict__ gbi, const float* __restrict__ gbh)
{
    __shared__ float      s_mw[144];
    __shared__ float      s_mb[12];
    __shared__ ulonglong2 sRZ[144];
    __shared__ ull        sN [144];
    __shared__ ull        sBR[12], sBZ[12], sBN[12];
    __shared__ float      sMA[NSB * 52];
    __shared__ float      sTR[48 * 72];

    int tid = threadIdx.x;
    int ns  = tid >> 2;
    int k   = tid & 3;
    int s   = blockIdx.y;
    int n0  = blockIdx.x * NSB + ns;
    int n1  = n0 + 32;

    for (int i = tid; i < 144; i += GTPB) {
        s_mw[i] = msgw[i];
        int d = i / 12, e = i - d * 12;
        ulonglong2 t;
        t.x = pack2(gwi[d * 12 + e],        gwh[d * 12 + e]);
        t.y = pack2(gwi[(12 + d) * 12 + e], gwh[(12 + d) * 12 + e]);
        sRZ[i] = t;
        sN[i]  = pack2(gwi[(24 + d) * 12 + e], gwh[(24 + d) * 12 + e]);
    }
    if (tid < 12) {
        s_mb[tid] = msgb[tid];
        sBR[tid] = pack2(gbi[tid] + gbh[tid], 0.f);
        sBZ[tid] = pack2(gbi[12 + tid] + gbh[12 + tid], 0.f);
        sBN[tid] = pack2(gbi[24 + tid], gbh[24 + tid]);
    }

    int base0 = n0 * SS + s, base1 = n1 * SS + s;
    float h0[12], h1[12];
    #pragma unroll
    for (int f = 0; f < 6; f++) {
        h0[f]     = nf [base0 * 24 + k * 6 + f];
        h0[6 + f] = pos[base0 * 24 + k * 6 + f];
        h1[f]     = nf [base1 * 24 + k * 6 + f];
        h1[6 + f] = pos[base1 * 24 + k * 6 + f];
    }
    float4 a40 = *reinterpret_cast<const float4*>(att + (size_t)base0 * 16 + k * 4);
    float4 a41 = *reinterpret_cast<const float4*>(att + (size_t)base1 * 16 + k * 4);

    __syncthreads();

    #pragma unroll 1
    for (int pass = 0; pass < 2; pass++) {
        float ma0[12], ma1[12];
        #pragma unroll
        for (int d = 0; d < 12; d++) {
            float acc0 = s_mb[d], acc1 = s_mb[d];
            #pragma unroll
            for (int e = 0; e < 12; e++) {
                float w = s_mw[d * 12 + e];
                acc0 += w * h0[e];
                acc1 += w * h1[e];
            }
            ma0[d] = acc0; ma1[d] = acc1;
        }
        __syncthreads();
        #pragma unroll
        for (int d = 0; d < 12; d++) {
            sMA[ns * 52 + k * 12 + d] = ma0[d];
            sMA[(ns + 32) * 52 + k * 12 + d] = ma1[d];
        }
        __syncthreads();

        ull gk0[12], gk1[12];
        {
            const float* m0 = sMA + ns * 52;
            const float* m1 = sMA + (ns + 32) * 52;
            #pragma unroll
            for (int e = 0; e < 12; e++) {
                float mv0 = a40.x * m0[e] + a40.y * m0[12 + e] +
                            a40.z * m0[24 + e] + a40.w * m0[36 + e];
                float mv1 = a41.x * m1[e] + a41.y * m1[12 + e] +
                            a41.z * m1[24 + e] + a41.w * m1[36 + e];
                gk0[e] = pack2(mv0, h0[e]);
                gk1[e] = pack2(mv1, h1[e]);
            }
        }

        float t0[12], t1[12];
        #pragma unroll 1
        for (int d = 0; d < 12; d++) {
            ull aR0 = sBR[d], aZ0 = sBZ[d], aN0 = sBN[d];
            ull aR1 = aR0,   aZ1 = aZ0,   aN1 = aN0;
            const ulonglong2* wrz = sRZ + d * 12;
            const ull*        wn  = sN  + d * 12;
            #pragma unroll
            for (int e = 0; e < 12; e++) {
                ulonglong2 w = wrz[e];
                ull wne = wn[e];
                fma2(aR0, w.x, gk0[e]); fma2(aZ0, w.y, gk0[e]); fma2(aN0, wne, gk0[e]);
                fma2(aR1, w.x, gk1[e]); fma2(aZ1, w.y, gk1[e]); fma2(aN1, wne, gk1[e]);
            }
            {
                float r = sigf(red2(aR0));
                float z = sigf(red2(aZ0));
                float nlo, nhi; unpack2(aN0, nlo, nhi);
                float nn = tanhf_(nlo + r * nhi);
                t0[d] = (1.0f - z) * nn + z * h0[d];
            }
            {
                float r = sigf(red2(aR1));
                float z = sigf(red2(aZ1));
                float nlo, nhi; unpack2(aN1, nlo, nhi);
                float nn = tanhf_(nlo + r * nhi);
                t1[d] = (1.0f - z) * nn + z * h1[d];
            }
        }
        #pragma unroll
        for (int d = 0; d < 12; d++) { h0[d] = t0[d]; h1[d] = t1[d]; }
    }

    __syncthreads();
    #pragma unroll
    for (int d = 0; d < 12; d++) {
        sTR[(d * 4 + k) * 72 + ns]      = h0[d];
        sTR[(d * 4 + k) * 72 + ns + 32] = h1[d];
    }
    __syncthreads();
    // pack feature pairs (rows 2jp, 2jp+1) -> ull store
    #pragma unroll
    for (int it = 0; it < 12; it++) {
        int idx = it * GTPB + tid;
        int jp = idx >> 6, col = idx & 63;
        ull v = pack2(sTR[(2 * jp) * 72 + col], sTR[(2 * jp + 1) * 72 + col]);
        g_xbuf[(size_t)(s * 24 + jp) * NB + blockIdx.x * NSB + col] = v;
    }
}

// ===========================================================================
// Kernel B: register-tiled bidirectional LSTM; NCB=64, 8 n per thread.
// Staging LDGs issued at step-top, STS deferred past the x-FMA block.
// ===========================================================================
#define O_W   0                         /* ull[48*SWS] = 74496 B */
#define O_ACT 74496                     /* ull[96*64]  = 49152 B */
#define O_B   (74496 + 49152)           /* float[192] */
#define SMEM_L (O_B + 768 + 16)

__global__ __launch_bounds__(TPB_L, 1) void lstm_rt_kernel(
    const float* __restrict__ wihF, const float* __restrict__ whhF,
    const float* __restrict__ bihF, const float* __restrict__ bhhF,
    const float* __restrict__ wihB, const float* __restrict__ whhB,
    const float* __restrict__ bihB, const float* __restrict__ bhhB)
{
    extern __shared__ char smc[];
    ull*   sW   = (ull*)(smc + O_W);
    ull*   sAct = (ull*)(smc + O_ACT);   // [row][64] with act_pos64 layout
    float* sB   = (float*)(smc + O_B);

    int tid = threadIdx.x;
    int d = tid >> 3;       // 0..47
    int q = tid & 7;        // 0..7
    int nb = blockIdx.x * NCB;

    // per-thread staging slots: i = tid + rr*TPB_L -> (kp, n)
    int skp[4], spos[4], sn_[4];
    #pragma unroll
    for (int rr = 0; rr < 4; rr++) {
        int i = tid + rr * TPB_L;
        skp[rr] = i >> 6;
        sn_[rr] = i & 63;
        spos[rr] = act_pos64(sn_[rr]);
    }

    #pragma unroll 1
    for (int dir = 0; dir < 2; dir++) {
        const float* wih = dir ? wihB : wihF;
        const float* whh = dir ? whhB : whhF;
        const float* bih = dir ? bihB : bihF;
        const float* bhh = dir ? bhhB : bhhF;

        __syncthreads();
        for (int i = tid; i < 9216; i += TPB_L) {
            int dd = i / 192;
            int r  = i - dd * 192;
            int kp = r >> 2, g = r & 3;
            int k0 = 2 * kp;
            float w0, w1;
            if (k0 < 48) {
                w0 = wih[(g * 48 + dd) * 48 + k0];
                w1 = wih[(g * 48 + dd) * 48 + k0 + 1];
            } else {
                w0 = whh[(g * 48 + dd) * 48 + (k0 - 48)];
                w1 = whh[(g * 48 + dd) * 48 + (k0 - 47)];
            }
            sW[dd * SWS + r] = pack2(w0, w1);
        }
        for (int i = tid; i < 192; i += TPB_L) {
            int dd = i >> 2, g = i & 3;
            sB[i] = bih[g * 48 + dd] + bhh[g * 48 + dd];
        }
        // zero h buf0; stage x step0 into x buf0
        {
            int s0 = dir ? (SS - 1) : 0;
            #pragma unroll
            for (int rr = 0; rr < 4; rr++) {
                sAct[(48 + skp[rr]) * 64 + spos[rr]] = 0ull;
                sAct[skp[rr] * 64 + spos[rr]] =
                    g_xbuf[(size_t)(s0 * 24 + skp[rr]) * NB + nb + sn_[rr]];
            }
        }
        __syncthreads();

        float b0 = sB[d * 4 + 0], b1 = sB[d * 4 + 1];
        float b2 = sB[d * 4 + 2], b3 = sB[d * 4 + 3];
        float c[8];
        #pragma unroll
        for (int u = 0; u < 8; u++) c[u] = 0.f;

        #pragma unroll 1
        for (int st = 0; st < SS; st++) {
            int xbase = (st & 1) * 24;

            // issue staging LDGs for st+1 (STS deferred past x-FMA)
            ull xv[4];
            if (st < SS - 1) {
                int sn = dir ? (SS - 2 - st) : (st + 1);
                #pragma unroll
                for (int rr = 0; rr < 4; rr++)
                    xv[rr] = g_xbuf[(size_t)(sn * 24 + skp[rr]) * NB + nb + sn_[rr]];
            }

            ull acc[4][8];
            #pragma unroll
            for (int g = 0; g < 4; g++)
                #pragma unroll
                for (int u = 0; u < 8; u++) acc[g][u] = 0ull;

            const ulonglong2* wrow = (const ulonglong2*)(sW + d * SWS);
            const ull* axr = sAct + xbase * 64;
            const ull* ahr = sAct + (48 + xbase) * 64;

            // x-part (covers the staging LDG latency)
            #pragma unroll
            for (int kp = 0; kp < 24; kp++) {
                ulonglong2 wA = wrow[kp * 2];
                ulonglong2 wB = wrow[kp * 2 + 1];
                #pragma unroll
                for (int g4 = 0; g4 < 4; g4++) {
                    ulonglong2 av = *(const ulonglong2*)(axr + kp * 64 + g4 * 16 + q * 2);
                    fma2(acc[0][2*g4],   wA.x, av.x); fma2(acc[1][2*g4],   wA.y, av.x);
                    fma2(acc[2][2*g4],   wB.x, av.x); fma2(acc[3][2*g4],   wB.y, av.x);
                    fma2(acc[0][2*g4+1], wA.x, av.y); fma2(acc[1][2*g4+1], wA.y, av.y);
                    fma2(acc[2][2*g4+1], wB.x, av.y); fma2(acc[3][2*g4+1], wB.y, av.y);
                }
            }

            // deferred STS of the prefetched x
            if (st < SS - 1) {
                int nbase = ((st + 1) & 1) * 24;
                #pragma unroll
                for (int rr = 0; rr < 4; rr++)
                    sAct[(nbase + skp[rr]) * 64 + spos[rr]] = xv[rr];
            }

            __syncthreads();   // h_{st} writes (prev tail) + x_{st+1} staging visible

            // h-part
            #pragma unroll
            for (int kp = 0; kp < 24; kp++) {
                ulonglong2 wA = wrow[48 + kp * 2];
                ulonglong2 wB = wrow[48 + kp * 2 + 1];
                #pragma unroll
                for (int g4 = 0; g4 < 4; g4++) {
                    ulonglong2 av = *(const ulonglong2*)(ahr + kp * 64 + g4 * 16 + q * 2);
                    fma2(acc[0][2*g4],   wA.x, av.x); fma2(acc[1][2*g4],   wA.y, av.x);
                    fma2(acc[2][2*g4],   wB.x, av.x); fma2(acc[3][2*g4],   wB.y, av.x);
                    fma2(acc[0][2*g4+1], wA.x, av.y); fma2(acc[1][2*g4+1], wA.y, av.y);
                    fma2(acc[2][2*g4+1], wB.x, av.y); fma2(acc[3][2*g4+1], wB.y, av.y);
                }
            }

            // epilogue: fma-pipe reductions first, then MUFU batch
            float pI[8], pF[8], pG[8], pO[8];
            #pragma unroll
            for (int u = 0; u < 8; u++) {
                pI[u] = red2(acc[0][u]) + b0;
                pF[u] = red2(acc[1][u]) + b1;
                pG[u] = red2(acc[2][u]) + b2;
                pO[u] = red2(acc[3][u]) + b3;
            }
            float hv[8];
            #pragma unroll
            for (int u = 0; u < 8; u++) {
                float ig = sigf(pI[u]), fg = sigf(pF[u]);
                float gg = tanhf_(pG[u]), og = sigf(pO[u]);
                float cn = fg * c[u] + ig * gg;
                c[u] = cn;
                hv[u] = og * tanhf_(cn);
            }

            if (st < SS - 1) {
                int nbase = ((st + 1) & 1) * 24;
                float* sAf = (float*)sAct;
                int kp_h = 48 + nbase + (d >> 1), par = d & 1;
                #pragma unroll
                for (int u = 0; u < 8; u++) {
                    int p = ((u >> 1) << 4) + q * 2 + (u & 1);
                    sAf[(kp_h * 64 + p) * 2 + par] = hv[u];
                }
            } else {
                float4 oa = make_float4(hv[0], hv[1], hv[2], hv[3]);
                float4 ob = make_float4(hv[4], hv[5], hv[6], hv[7]);
                *(float4*)&g_hst[dir][(size_t)d * NB + nb + q * 8]     = oa;
                *(float4*)&g_hst[dir][(size_t)d * NB + nb + q * 8 + 4] = ob;
            }
        } // st
    } // dir
}

// ===========================================================================
// Kernel C: MLP head, one thread per n (f32x2 pairs), smem weights
// ===========================================================================
__global__ __launch_bounds__(256) void mlp_kernel(
    const float* __restrict__ e1w, const float* __restrict__ e1b,
    const float* __restrict__ e2w, const float* __restrict__ e2b,
    const float* __restrict__ e3w, const float* __restrict__ e3b,
    float* __restrict__ out)
{
    __shared__ ull   m1p[2304];
    __shared__ float m1b[48], m2[1728], m2b[36], m3[216], m3b[6];

    int tid = threadIdx.x;
    for (int i = tid; i < 2304; i += 256) {
        int ii = i / 48, j = i - ii * 48;
        m1p[i] = pack2(e1w[ii * 96 + j], e1w[ii * 96 + 48 + j]);
    }
    for (int i = tid; i < 1728; i += 256) m2[i] = e2w[i];
    for (int i = tid; i < 216;  i += 256) m3[i] = e3w[i];
    if (tid < 48) m1b[tid] = e1b[tid];
    if (tid < 36) m2b[tid] = e2b[tid];
    if (tid < 6)  m3b[tid] = e3b[tid];
    __syncthreads();

    int n = blockIdx.x * 256 + tid;

    ull av[48];
    #pragma unroll
    for (int j = 0; j < 48; j++)
        av[j] = pack2(g_hst[0][(size_t)j * NB + n], g_hst[1][(size_t)j * NB + n]);

    float x1l[48];
    #pragma unroll 1
    for (int i = 0; i < 48; i++) {
        ull acc = pack2(m1b[i], 0.f);
        const ull* w = m1p + i * 48;
        #pragma unroll
        for (int j = 0; j < 48; j++) fma2(acc, w[j], av[j]);
        x1l[i] = fmaxf(red2(acc), 0.f);
    }
    #pragma unroll
    for (int j = 0; j < 24; j++) av[j] = pack2(x1l[2*j], x1l[2*j+1]);
    const ull* m2p = (const ull*)m2;
    float x2l[36];
    #pragma unroll 1
    for (int i = 0; i < 36; i++) {
        ull acc = pack2(m2b[i], 0.f);
        const ull* w = m2p + i * 24;
        #pragma unroll
        for (int j = 0; j < 24; j++) fma2(acc, w[j], av[j]);
        x2l[i] = fmaxf(red2(acc), 0.f);
    }
    #pragma unroll
    for (int j = 0; j < 18; j++) av[j] = pack2(x2l[2*j], x2l[2*j+1]);
    const ull* m3p = (const ull*)m3;
    #pragma unroll
    for (int cc = 0; cc < 6; cc++) {
        ull acc = pack2(m3b[cc], 0.f);
        const ull* w = m3p + cc * 18;
        #pragma unroll
        for (int j = 0; j < 18; j++) fma2(acc, w[j], av[j]);
        out[(size_t)n * 6 + cc] = red2(acc);
    }
}

// ===========================================================================
extern "C" void kernel_launch(void* const* d_in, const int* in_sizes, int n_in,
                              void* d_out, int out_size)
{
    const float* nf   = (const float*)d_in[0];
    const float* pos  = (const float*)d_in[1];
    const float* att  = (const float*)d_in[2];
    const float* msgw = (const float*)d_in[3];
    const float* msgb = (const float*)d_in[4];
    const float* gwi  = (const float*)d_in[5];
    const float* gwh  = (const float*)d_in[6];
    const float* gbi  = (const float*)d_in[7];
    const float* gbh  = (const float*)d_in[8];
    const float* wihF = (const float*)d_in[9];
    const float* whhF = (const float*)d_in[10];
    const float* bihF = (const float*)d_in[11];
    const float* bhhF = (const float*)d_in[12];
    const float* wihB = (const float*)d_in[13];
    const float* whhB = (const float*)d_in[14];
    const float* bihB = (const float*)d_in[15];
    const float* bhhB = (const float*)d_in[16];
    const float* e1w  = (const float*)d_in[17];
    const float* e1b  = (const float*)d_in[18];
    const float* e2w  = (const float*)d_in[19];
    const float* e2b  = (const float*)d_in[20];
    const float* e3w  = (const float*)d_in[21];
    const float* e3b  = (const float*)d_in[22];
    float* out = (float*)d_out;

    cudaFuncSetAttribute(lstm_rt_kernel,
                         cudaFuncAttributeMaxDynamicSharedMemorySize, SMEM_L);

    dim3 gA(NB / NSB, SS);
    gnn_kernel<<<gA, GTPB>>>(nf, pos, att, msgw, msgb, gwi, gwh, gbi, gbh);
    lstm_rt_kernel<<<NB / NCB, TPB_L, SMEM_L>>>(
        wihF, whhF, bihF, bhhF, wihB, whhB, bihB, bhhB);
    mlp_kernel<<<NB / 256, 256>>>(e1w, e1b, e2w, e2b, e3w, e3b, out);
}

// round 17
// speedup vs baseline: 1.3009x; 1.0174x over previous
#include <cuda_runtime.h>
#include <cuda_bf16.h>
#include <cstdint>

#define NB 65536
#define SS 5
#define KK 4
#define DD 12
#define HH 48
#define NCB 64        // batch rows per LSTM CTA
#define TPB_L 384     // 48 d  x  8 q (8 n per thread)
#define SWS 194       // padded ull-stride per d row (1552 B, != 0 mod 128)

typedef unsigned long long ull;

__device__ ull   g_xbuf[SS * 24 * NB];        // [s][feat-pair][n] packed pairs
__device__ float g_hst[2][(size_t)HH * NB];   // final hidden per dir, [d][n]
__device__ ull   g_wpk[2 * 48 * SWS];         // prepacked padded weight image
__device__ float g_bpk[2 * 192];              // prepacked combined biases

// ---------------- helpers ----------------
__device__ __forceinline__ float sigf(float x) {
    return __fdividef(1.0f, 1.0f + __expf(-x));
}
__device__ __forceinline__ float tanhf_(float x) {
    return 1.0f - __fdividef(2.0f, __expf(2.0f * x) + 1.0f);
}
__device__ __forceinline__ ull pack2(float lo, float hi) {
    ull r; asm("mov.b64 %0, {%1, %2};" : "=l"(r) : "f"(lo), "f"(hi)); return r;
}
__device__ __forceinline__ void unpack2(ull v, float& lo, float& hi) {
    asm("mov.b64 {%0, %1}, %2;" : "=f"(lo), "=f"(hi) : "l"(v));
}
__device__ __forceinline__ float red2(ull v) {
    float lo, hi; unpack2(v, lo, hi); return lo + hi;
}
__device__ __forceinline__ void fma2(ull& acc, ull a, ull b) {
    asm("fma.rn.f32x2 %0, %1, %2, %0;" : "+l"(acc) : "l"(a), "l"(b));
}

// n (0..63) -> ull position in a 64-ull act row
__device__ __forceinline__ int act_pos64(int n) {
    int q = n >> 3, u = n & 7;
    return ((u >> 1) << 4) + q * 2 + (u & 1);
}

// ===========================================================================
// Kernel 0: one-time weight prepack into the exact padded sW image
// ===========================================================================
__global__ __launch_bounds__(256) void wpack_kernel(
    const float* __restrict__ wihF, const float* __restrict__ whhF,
    const float* __restrict__ bihF, const float* __restrict__ bhhF,
    const float* __restrict__ wihB, const float* __restrict__ whhB,
    const float* __restrict__ bihB, const float* __restrict__ bhhB)
{
    int i = blockIdx.x * 256 + threadIdx.x;
    if (i < 2 * 9216) {
        int dir = i / 9216;
        int r0  = i - dir * 9216;
        int dd = r0 / 192;
        int r  = r0 - dd * 192;
        int kp = r >> 2, g = r & 3;
        int k0 = 2 * kp;
        const float* wih = dir ? wihB : wihF;
        const float* whh = dir ? whhB : whhF;
        float w0, w1;
        if (k0 < 48) {
            w0 = wih[(g * 48 + dd) * 48 + k0];
            w1 = wih[(g * 48 + dd) * 48 + k0 + 1];
        } else {
            w0 = whh[(g * 48 + dd) * 48 + (k0 - 48)];
            w1 = whh[(g * 48 + dd) * 48 + (k0 - 47)];
        }
        g_wpk[dir * 48 * SWS + dd * SWS + r] = pack2(w0, w1);
    }
    if (i < 2 * 192) {
        int dir = i / 192, j = i - dir * 192;
        int dd = j >> 2, g = j & 3;
        const float* bih = dir ? bihB : bihF;
        const float* bhh = dir ? bhhB : bhhF;
        g_bpk[dir * 192 + j] = bih[g * 48 + dd] + bhh[g * 48 + dd];
    }
}

// ===========================================================================
// Kernel A: GNN — 4 threads per (n,s) pair, each thread handles TWO pairs.
// (identical to R16 passing version)
// ===========================================================================
#define GTPB 128
#define NSB  64

__global__ __launch_bounds__(GTPB) void gnn_kernel(
    const float* __restrict__ nf, const float* __restrict__ pos,
    const float* __restrict__ att,
    const float* __restrict__ msgw, const float* __restrict__ msgb,
    const float* __restrict__ gwi, const float* __restrict__ gwh,
    const float* __restrict__ gbi, const float* __restrict__ gbh)
{
    __shared__ float      s_mw[144];
    __shared__ float      s_mb[12];
    __shared__ ulonglong2 sRZ[144];
    __shared__ ull        sN [144];
    __shared__ ull        sBR[12], sBZ[12], sBN[12];
    __shared__ float      sMA[NSB * 52];
    __shared__ float      sTR[48 * 72];

    int tid = threadIdx.x;
    int ns  = tid >> 2;
    int k   = tid & 3;
    int s   = blockIdx.y;
    int n0  = blockIdx.x * NSB + ns;
    int n1  = n0 + 32;

    for (int i = tid; i < 144; i += GTPB) {
        s_mw[i] = msgw[i];
        int d = i / 12, e = i - d * 12;
        ulonglong2 t;
        t.x = pack2(gwi[d * 12 + e],        gwh[d * 12 + e]);
        t.y = pack2(gwi[(12 + d) * 12 + e], gwh[(12 + d) * 12 + e]);
        sRZ[i] = t;
        sN[i]  = pack2(gwi[(24 + d) * 12 + e], gwh[(24 + d) * 12 + e]);
    }
    if (tid < 12) {
        s_mb[tid] = msgb[tid];
        sBR[tid] = pack2(gbi[tid] + gbh[tid], 0.f);
        sBZ[tid] = pack2(gbi[12 + tid] + gbh[12 + tid], 0.f);
        sBN[tid] = pack2(gbi[24 + tid], gbh[24 + tid]);
    }

    int base0 = n0 * SS + s, base1 = n1 * SS + s;
    float h0[12], h1[12];
    #pragma unroll
    for (int f = 0; f < 6; f++) {
        h0[f]     = nf [base0 * 24 + k * 6 + f];
        h0[6 + f] = pos[base0 * 24 + k * 6 + f];
        h1[f]     = nf [base1 * 24 + k * 6 + f];
        h1[6 + f] = pos[base1 * 24 + k * 6 + f];
    }
    float4 a40 = *reinterpret_cast<const float4*>(att + (size_t)base0 * 16 + k * 4);
    float4 a41 = *reinterpret_cast<const float4*>(att + (size_t)base1 * 16 + k * 4);

    __syncthreads();

    #pragma unroll 1
    for (int pass = 0; pass < 2; pass++) {
        float ma0[12], ma1[12];
        #pragma unroll
        for (int d = 0; d < 12; d++) {
            float acc0 = s_mb[d], acc1 = s_mb[d];
            #pragma unroll
            for (int e = 0; e < 12; e++) {
                float w = s_mw[d * 12 + e];
                acc0 += w * h0[e];
                acc1 += w * h1[e];
            }
            ma0[d] = acc0; ma1[d] = acc1;
        }
        __syncthreads();
        #pragma unroll
        for (int d = 0; d < 12; d++) {
            sMA[ns * 52 + k * 12 + d] = ma0[d];
            sMA[(ns + 32) * 52 + k * 12 + d] = ma1[d];
        }
        __syncthreads();

        ull gk0[12], gk1[12];
        {
            const float* m0 = sMA + ns * 52;
            const float* m1 = sMA + (ns + 32) * 52;
            #pragma unroll
            for (int e = 0; e < 12; e++) {
                float mv0 = a40.x * m0[e] + a40.y * m0[12 + e] +
                            a40.z * m0[24 + e] + a40.w * m0[36 + e];
                float mv1 = a41.x * m1[e] + a41.y * m1[12 + e] +
                            a41.z * m1[24 + e] + a41.w * m1[36 + e];
                gk0[e] = pack2(mv0, h0[e]);
                gk1[e] = pack2(mv1, h1[e]);
            }
        }

        float t0[12], t1[12];
        #pragma unroll 1
        for (int d = 0; d < 12; d++) {
            ull aR0 = sBR[d], aZ0 = sBZ[d], aN0 = sBN[d];
            ull aR1 = aR0,   aZ1 = aZ0,   aN1 = aN0;
            const ulonglong2* wrz = sRZ + d * 12;
            const ull*        wn  = sN  + d * 12;
            #pragma unroll
            for (int e = 0; e < 12; e++) {
                ulonglong2 w = wrz[e];
                ull wne = wn[e];
                fma2(aR0, w.x, gk0[e]); fma2(aZ0, w.y, gk0[e]); fma2(aN0, wne, gk0[e]);
                fma2(aR1, w.x, gk1[e]); fma2(aZ1, w.y, gk1[e]); fma2(aN1, wne, gk1[e]);
            }
            {
                float r = sigf(red2(aR0));
                float z = sigf(red2(aZ0));
                float nlo, nhi; unpack2(aN0, nlo, nhi);
                float nn = tanhf_(nlo + r * nhi);
                t0[d] = (1.0f - z) * nn + z * h0[d];
            }
            {
                float r = sigf(red2(aR1));
                float z = sigf(red2(aZ1));
                float nlo, nhi; unpack2(aN1, nlo, nhi);
                float nn = tanhf_(nlo + r * nhi);
                t1[d] = (1.0f - z) * nn + z * h1[d];
            }
        }
        #pragma unroll
        for (int d = 0; d < 12; d++) { h0[d] = t0[d]; h1[d] = t1[d]; }
    }

    __syncthreads();
    #pragma unroll
    for (int d = 0; d < 12; d++) {
        sTR[(d * 4 + k) * 72 + ns]      = h0[d];
        sTR[(d * 4 + k) * 72 + ns + 32] = h1[d];
    }
    __syncthreads();
    #pragma unroll
    for (int it = 0; it < 12; it++) {
        int idx = it * GTPB + tid;
        int jp = idx >> 6, col = idx & 63;
        ull v = pack2(sTR[(2 * jp) * 72 + col], sTR[(2 * jp + 1) * 72 + col]);
        g_xbuf[(size_t)(s * 24 + jp) * NB + blockIdx.x * NSB + col] = v;
    }
}

// ===========================================================================
// Kernel B: register-tiled bidirectional LSTM; staging is a wide copy of the
// prepacked weight image.
// ===========================================================================
#define O_W   0                         /* ull[48*SWS] = 74496 B */
#define O_ACT 74496                     /* ull[96*64]  = 49152 B */
#define O_B   (74496 + 49152)           /* float[192] */
#define SMEM_L (O_B + 768 + 16)

__global__ __launch_bounds__(TPB_L, 1) void lstm_rt_kernel()
{
    extern __shared__ char smc[];
    ull*   sW   = (ull*)(smc + O_W);
    ull*   sAct = (ull*)(smc + O_ACT);   // [row][64] with act_pos64 layout
    float* sB   = (float*)(smc + O_B);

    int tid = threadIdx.x;
    int d = tid >> 3;       // 0..47
    int q = tid & 7;        // 0..7
    int nb = blockIdx.x * NCB;

    int skp[4], spos[4], sn_[4];
    #pragma unroll
    for (int rr = 0; rr < 4; rr++) {
        int i = tid + rr * TPB_L;
        skp[rr] = i >> 6;
        sn_[rr] = i & 63;
        spos[rr] = act_pos64(sn_[rr]);
    }

    #pragma unroll 1
    for (int dir = 0; dir < 2; dir++) {
        __syncthreads();
        // wide copy of prepacked weights (48*SWS = 9312 ull = 4656 u128)
        {
            const ulonglong2* src = (const ulonglong2*)(g_wpk + dir * 48 * SWS);
            ulonglong2* dst = (ulonglong2*)sW;
            for (int i = tid; i < 4656; i += TPB_L) dst[i] = src[i];
            if (tid < 192) sB[tid] = g_bpk[dir * 192 + tid];
        }
        // zero h buf0; stage x step0 into x buf0
        {
            int s0 = dir ? (SS - 1) : 0;
            #pragma unroll
            for (int rr = 0; rr < 4; rr++) {
                sAct[(48 + skp[rr]) * 64 + spos[rr]] = 0ull;
                sAct[skp[rr] * 64 + spos[rr]] =
                    g_xbuf[(size_t)(s0 * 24 + skp[rr]) * NB + nb + sn_[rr]];
            }
        }
        __syncthreads();

        float b0 = sB[d * 4 + 0], b1 = sB[d * 4 + 1];
        float b2 = sB[d * 4 + 2], b3 = sB[d * 4 + 3];
        float c[8];
        #pragma unroll
        for (int u = 0; u < 8; u++) c[u] = 0.f;

        #pragma unroll 1
        for (int st = 0; st < SS; st++) {
            int xbase = (st & 1) * 24;

            ull xv[4];
            if (st < SS - 1) {
                int sn = dir ? (SS - 2 - st) : (st + 1);
                #pragma unroll
                for (int rr = 0; rr < 4; rr++)
                    xv[rr] = g_xbuf[(size_t)(sn * 24 + skp[rr]) * NB + nb + sn_[rr]];
            }

            ull acc[4][8];
            #pragma unroll
            for (int g = 0; g < 4; g++)
                #pragma unroll
                for (int u = 0; u < 8; u++) acc[g][u] = 0ull;

            const ulonglong2* wrow = (const ulonglong2*)(sW + d * SWS);
            const ull* axr = sAct + xbase * 64;
            const ull* ahr = sAct + (48 + xbase) * 64;

            #pragma unroll
            for (int kp = 0; kp < 24; kp++) {
                ulonglong2 wA = wrow[kp * 2];
                ulonglong2 wB = wrow[kp * 2 + 1];
                #pragma unroll
                for (int g4 = 0; g4 < 4; g4++) {
                    ulonglong2 av = *(const ulonglong2*)(axr + kp * 64 + g4 * 16 + q * 2);
                    fma2(acc[0][2*g4],   wA.x, av.x); fma2(acc[1][2*g4],   wA.y, av.x);
                    fma2(acc[2][2*g4],   wB.x, av.x); fma2(acc[3][2*g4],   wB.y, av.x);
                    fma2(acc[0][2*g4+1], wA.x, av.y); fma2(acc[1][2*g4+1], wA.y, av.y);
                    fma2(acc[2][2*g4+1], wB.x, av.y); fma2(acc[3][2*g4+1], wB.y, av.y);
                }
            }

            if (st < SS - 1) {
                int nbase = ((st + 1) & 1) * 24;
                #pragma unroll
                for (int rr = 0; rr < 4; rr++)
                    sAct[(nbase + skp[rr]) * 64 + spos[rr]] = xv[rr];
            }

            __syncthreads();

            #pragma unroll
            for (int kp = 0; kp < 24; kp++) {
                ulonglong2 wA = wrow[48 + kp * 2];
                ulonglong2 wB = wrow[48 + kp * 2 + 1];
                #pragma unroll
                for (int g4 = 0; g4 < 4; g4++) {
                    ulonglong2 av = *(const ulonglong2*)(ahr + kp * 64 + g4 * 16 + q * 2);
                    fma2(acc[0][2*g4],   wA.x, av.x); fma2(acc[1][2*g4],   wA.y, av.x);
                    fma2(acc[2][2*g4],   wB.x, av.x); fma2(acc[3][2*g4],   wB.y, av.x);
                    fma2(acc[0][2*g4+1], wA.x, av.y); fma2(acc[1][2*g4+1], wA.y, av.y);
                    fma2(acc[2][2*g4+1], wB.x, av.y); fma2(acc[3][2*g4+1], wB.y, av.y);
                }
            }

            float pI[8], pF[8], pG[8], pO[8];
            #pragma unroll
            for (int u = 0; u < 8; u++) {
                pI[u] = red2(acc[0][u]) + b0;
                pF[u] = red2(acc[1][u]) + b1;
                pG[u] = red2(acc[2][u]) + b2;
                pO[u] = red2(acc[3][u]) + b3;
            }
            float hv[8];
            #pragma unroll
            for (int u = 0; u < 8; u++) {
                float ig = sigf(pI[u]), fg = sigf(pF[u]);
                float gg = tanhf_(pG[u]), og = sigf(pO[u]);
                float cn = fg * c[u] + ig * gg;
                c[u] = cn;
                hv[u] = og * tanhf_(cn);
            }

            if (st < SS - 1) {
                int nbase = ((st + 1) & 1) * 24;
                float* sAf = (float*)sAct;
                int kp_h = 48 + nbase + (d >> 1), par = d & 1;
                #pragma unroll
                for (int u = 0; u < 8; u++) {
                    int p = ((u >> 1) << 4) + q * 2 + (u & 1);
                    sAf[(kp_h * 64 + p) * 2 + par] = hv[u];
                }
            } else {
                float4 oa = make_float4(hv[0], hv[1], hv[2], hv[3]);
                float4 ob = make_float4(hv[4], hv[5], hv[6], hv[7]);
                *(float4*)&g_hst[dir][(size_t)d * NB + nb + q * 8]     = oa;
                *(float4*)&g_hst[dir][(size_t)d * NB + nb + q * 8 + 4] = ob;
            }
        } // st
    } // dir
}

// ===========================================================================
// Kernel C: MLP head, one thread per n (f32x2 pairs), smem weights
// ===========================================================================
__global__ __launch_bounds__(256) void mlp_kernel(
    const float* __restrict__ e1w, const float* __restrict__ e1b,
    const float* __restrict__ e2w, const float* __restrict__ e2b,
    const float* __restrict__ e3w, const float* __restrict__ e3b,
    float* __restrict__ out)
{
    __shared__ ull   m1p[2304];
    __shared__ float m1b[48], m2[1728], m2b[36], m3[216], m3b[6];

    int tid = threadIdx.x;
    for (int i = tid; i < 2304; i += 256) {
        int ii = i / 48, j = i - ii * 48;
        m1p[i] = pack2(e1w[ii * 96 + j], e1w[ii * 96 + 48 + j]);
    }
    for (int i = tid; i < 1728; i += 256) m2[i] = e2w[i];
    for (int i = tid; i < 216;  i += 256) m3[i] = e3w[i];
    if (tid < 48) m1b[tid] = e1b[tid];
    if (tid < 36) m2b[tid] = e2b[tid];
    if (tid < 6)  m3b[tid] = e3b[tid];
    __syncthreads();

    int n = blockIdx.x * 256 + tid;

    ull av[48];
    #pragma unroll
    for (int j = 0; j < 48; j++)
        av[j] = pack2(g_hst[0][(size_t)j * NB + n], g_hst[1][(size_t)j * NB + n]);

    float x1l[48];
    #pragma unroll 1
    for (int i = 0; i < 48; i++) {
        ull acc = pack2(m1b[i], 0.f);
        const ull* w = m1p + i * 48;
        #pragma unroll
        for (int j = 0; j < 48; j++) fma2(acc, w[j], av[j]);
        x1l[i] = fmaxf(red2(acc), 0.f);
    }
    #pragma unroll
    for (int j = 0; j < 24; j++) av[j] = pack2(x1l[2*j], x1l[2*j+1]);
    const ull* m2p = (const ull*)m2;
    float x2l[36];
    #pragma unroll 1
    for (int i = 0; i < 36; i++) {
        ull acc = pack2(m2b[i], 0.f);
        const ull* w = m2p + i * 24;
        #pragma unroll
        for (int j = 0; j < 24; j++) fma2(acc, w[j], av[j]);
        x2l[i] = fmaxf(red2(acc), 0.f);
    }
    #pragma unroll
    for (int j = 0; j < 18; j++) av[j] = pack2(x2l[2*j], x2l[2*j+1]);
    const ull* m3p = (const ull*)m3;
    #pragma unroll
    for (int cc = 0; cc < 6; cc++) {
        ull acc = pack2(m3b[cc], 0.f);
        const ull* w = m3p + cc * 18;
        #pragma unroll
        for (int j = 0; j < 18; j++) fma2(acc, w[j], av[j]);
        out[(size_t)n * 6 + cc] = red2(acc);
    }
}

// ===========================================================================
extern "C" void kernel_launch(void* const* d_in, const int* in_sizes, int n_in,
                              void* d_out, int out_size)
{
    const float* nf   = (const float*)d_in[0];
    const float* pos  = (const float*)d_in[1];
    const float* att  = (const float*)d_in[2];
    const float* msgw = (const float*)d_in[3];
    const float* msgb = (const float*)d_in[4];
    const float* gwi  = (const float*)d_in[5];
    const float* gwh  = (const float*)d_in[6];
    const float* gbi  = (const float*)d_in[7];
    const float* gbh  = (const float*)d_in[8];
    const float* wihF = (const float*)d_in[9];
    const float* whhF = (const float*)d_in[10];
    const float* bihF = (const float*)d_in[11];
    const float* bhhF = (const float*)d_in[12];
    const float* wihB = (const float*)d_in[13];
    const float* whhB = (const float*)d_in[14];
    const float* bihB = (const float*)d_in[15];
    const float* bhhB = (const float*)d_in[16];
    const float* e1w  = (const float*)d_in[17];
    const float* e1b  = (const float*)d_in[18];
    const float* e2w  = (const float*)d_in[19];
    const float* e2b  = (const float*)d_in[20];
    const float* e3w  = (const float*)d_in[21];
    const float* e3b  = (const float*)d_in[22];
    float* out = (float*)d_out;

    cudaFuncSetAttribute(lstm_rt_kernel,
                         cudaFuncAttributeMaxDynamicSharedMemorySize, SMEM_L);

    wpack_kernel<<<(2 * 9216 + 255) / 256, 256>>>(
        wihF, whhF, bihF, bhhF, wihB, whhB, bihB, bhhB);
    dim3 gA(NB / NSB, SS);
    gnn_kernel<<<gA, GTPB>>>(nf, pos, att, msgw, msgb, gwi, gwh, gbi, gbh);
    lstm_rt_kernel<<<NB / NCB, TPB_L, SMEM_L>>>();
    mlp_kernel<<<NB / 256, 256>>>(e1w, e1b, e2w, e2b, e3w, e3b, out);
}